// round 8
// baseline (speedup 1.0000x reference)
#include <cuda_runtime.h>
#include <cuda_fp16.h>
#include <cstdint>
#include <math.h>

#define BATCH 4
#define SEQ   2048
#define HID   2048
#define INTER 5504
#define MTOK  (BATCH*SEQ)            // 8192
#define OUT_ELEMS ((long)MTOK*HID)   // 16777216

// ---------------- scratch ----------------
__device__ __half g_Xh [(long)MTOK*HID];
__device__ __half g_Wgh[(long)INTER*HID];
__device__ __half g_Wuh[(long)INTER*HID];
__device__ __half g_Wdh[(long)HID*INTER];
__device__ __half g_inter[(long)MTOK*INTER];
__device__ float  g_rowsq[INTER];
__device__ float  g_part [32L*INTER];

// ---------------- helpers ----------------
__device__ __forceinline__ uint32_t smem_u32(const void* p){
    uint32_t a;
    asm("{ .reg .u64 t; cvta.to.shared.u64 t, %1; cvt.u32.u64 %0, t; }" : "=r"(a) : "l"(p));
    return a;
}
__device__ __forceinline__ void cpa16(uint32_t dst, const void* src){
    asm volatile("cp.async.cg.shared.global [%0], [%1], 16;" :: "r"(dst), "l"(src));
}
__device__ __forceinline__ void ldsm4(uint32_t r[4], uint32_t addr){
    asm volatile("ldmatrix.sync.aligned.m8n8.x4.shared.b16 {%0,%1,%2,%3}, [%4];"
                 : "=r"(r[0]), "=r"(r[1]), "=r"(r[2]), "=r"(r[3]) : "r"(addr));
}
__device__ __forceinline__ void mma_f16(float c[4],
                                        uint32_t a0, uint32_t a1, uint32_t a2, uint32_t a3,
                                        uint32_t b0, uint32_t b1) {
    asm volatile(
        "mma.sync.aligned.m16n8k16.row.col.f32.f16.f16.f32 "
        "{%0,%1,%2,%3}, {%4,%5,%6,%7}, {%8,%9}, {%0,%1,%2,%3};"
        : "+f"(c[0]), "+f"(c[1]), "+f"(c[2]), "+f"(c[3])
        : "r"(a0), "r"(a1), "r"(a2), "r"(a3), "r"(b0), "r"(b1));
}
#define CP_COMMIT() asm volatile("cp.async.commit_group;" ::: "memory")
#define CP_WAIT(n)  asm volatile("cp.async.wait_group %0;" :: "n"(n) : "memory")

// 128B-row XOR swizzle (conflict-free)
#define SWZB(o) ((o) ^ (((o) >> 3) & 0x70))

// ============================================================================
// Fused gate/up GEMM + SwiGLU. 512 threads, block 128m x 128n (both mats).
// K-chunk 128 halves, stored as TWO 128B-row sub-tiles of 16KB each.
// Stage = A(32K) + Bg(32K) + Bu(32K) = 96KB; 2 stages = 192KB, 1 CTA/SM,
// 16 warps (4/SMSP). 16 barriers per tile (vs 32 before).
// ============================================================================
#define GU_SUB_B   16384
#define GU_BG_OFF  32768
#define GU_BU_OFF  65536
#define GU_STAGE_B 98304
#define GU_SMEM_BYTES (2*GU_STAGE_B)   // 196608

__global__ void __launch_bounds__(512,1)
gemm_gu(const __half* __restrict__ X, const __half* __restrict__ Wg,
        const __half* __restrict__ Wu, __half* __restrict__ inter)
{
    extern __shared__ char smemc[];
    const uint32_t sb = smem_u32(smemc);

    const int tid  = threadIdx.x;
    const int wid  = tid >> 5;     // 0..15
    const int lane = tid & 31;
    const int grp  = lane >> 2;
    const int tig  = lane & 3;
    const int wm   = wid >> 2;     // 0..3  (m warp tile 32)
    const int wn   = wid & 3;      // 0..3  (n warp tile 32)

    const int NBN = INTER/128;     // 43
    const int GM  = 16;
    int bid = blockIdx.x;
    int g   = bid / (GM*NBN);
    int r   = bid % (GM*NBN);
    const long bm = (long)(g*GM + (r % GM)) * 128;
    const int  bn = (r / GM) * 128;

    // load mapping: 1024 16B-units per sub-tile, 512 threads -> 2 iters (i)
    // row_i = (tid>>3) + 64*i (0..127), c = tid&7
    const int rowb = tid >> 3;
    const int cA   = (tid & 7) * 8;   // halves

    const __half* Ag0 = X  + (bm + rowb)*(long)HID + cA;
    const __half* Ag1 = X  + (bm + rowb + 64)*(long)HID + cA;
    const __half* Gg0 = Wg + (long)(bn + rowb)*HID + cA;
    const __half* Gg1 = Wg + (long)(bn + rowb + 64)*HID + cA;
    const __half* Ug0 = Wu + (long)(bn + rowb)*HID + cA;
    const __half* Ug1 = Wu + (long)(bn + rowb + 64)*HID + cA;

    uint32_t stoff0 = SWZB((uint32_t)(rowb*128 + (tid & 7)*16));
    uint32_t stoff1 = SWZB((uint32_t)((rowb + 64)*128 + (tid & 7)*16));

    float acc_g[2][4][4], acc_u[2][4][4];
#pragma unroll
    for (int mi = 0; mi < 2; mi++)
#pragma unroll
        for (int ni = 0; ni < 4; ni++)
#pragma unroll
            for (int q = 0; q < 4; q++) { acc_g[mi][ni][q] = 0.f; acc_u[mi][ni][q] = 0.f; }

    // ldmatrix per-lane geometry (per sub-tile)
    const uint32_t swzm = (lane & 7) * 16;
    const uint32_t browA = (wm*32 + (lane & 15)) * 128;
    const uint32_t akbe = ((lane >> 4) & 1) * 16;
    const uint32_t browB = (wn*32 + ((lane >> 4) & 1)*8 + (lane & 7)) * 128;
    const uint32_t bkbe = ((lane >> 3) & 1) * 16;
    uint32_t akb4[4], bkb4[4];
#pragma unroll
    for (int kw = 0; kw < 4; kw++) {
        akb4[kw] = ((uint32_t)(kw*32) + akbe) ^ swzm;
        bkb4[kw] = ((uint32_t)(kw*32) + bkbe) ^ swzm;
    }

    const int nK = HID/128;   // 16

    // preload chunk 0 into stage 0
    {
        const uint32_t st = sb;
#pragma unroll
        for (int sk = 0; sk < 2; sk++) {
            const int k0 = sk*64;
            cpa16(st + sk*GU_SUB_B + stoff0,             Ag0 + k0);
            cpa16(st + sk*GU_SUB_B + stoff1,             Ag1 + k0);
            cpa16(st + GU_BG_OFF + sk*GU_SUB_B + stoff0, Gg0 + k0);
            cpa16(st + GU_BG_OFF + sk*GU_SUB_B + stoff1, Gg1 + k0);
            cpa16(st + GU_BU_OFF + sk*GU_SUB_B + stoff0, Ug0 + k0);
            cpa16(st + GU_BU_OFF + sk*GU_SUB_B + stoff1, Ug1 + k0);
        }
        CP_COMMIT();
    }

    uint32_t s = 0;
    for (int j = 0; j < nK; j++) {
        CP_WAIT(0);
        __syncthreads();

        if (j + 1 < nK) {
            const int k0 = (j+1)*128;
            const uint32_t st = sb + (s ^ 1)*GU_STAGE_B;
#pragma unroll
            for (int sk = 0; sk < 2; sk++) {
                const int kk = k0 + sk*64;
                cpa16(st + sk*GU_SUB_B + stoff0,             Ag0 + kk);
                cpa16(st + sk*GU_SUB_B + stoff1,             Ag1 + kk);
                cpa16(st + GU_BG_OFF + sk*GU_SUB_B + stoff0, Gg0 + kk);
                cpa16(st + GU_BG_OFF + sk*GU_SUB_B + stoff1, Gg1 + kk);
                cpa16(st + GU_BU_OFF + sk*GU_SUB_B + stoff0, Ug0 + kk);
                cpa16(st + GU_BU_OFF + sk*GU_SUB_B + stoff1, Ug1 + kk);
            }
        }
        CP_COMMIT();

        const uint32_t As = sb + s*GU_STAGE_B;
        const uint32_t Gs = As + GU_BG_OFF;
        const uint32_t Us = As + GU_BU_OFF;

#pragma unroll
        for (int ks = 0; ks < 8; ks++) {
            const uint32_t sub = (ks >> 2) ? GU_SUB_B : 0u;
            const int kw = ks & 3;
            uint32_t af[2][4], bg0[4], bg1[4], bu0[4], bu1[4];
            ldsm4(af[0], As + sub + browA + akb4[kw]);
            ldsm4(af[1], As + sub + browA + 2048 + akb4[kw]);
            ldsm4(bg0, Gs + sub + browB + bkb4[kw]);
            ldsm4(bg1, Gs + sub + browB + 2048 + bkb4[kw]);
            ldsm4(bu0, Us + sub + browB + bkb4[kw]);
            ldsm4(bu1, Us + sub + browB + 2048 + bkb4[kw]);
#pragma unroll
            for (int mi = 0; mi < 2; mi++) {
#pragma unroll
                for (int ni = 0; ni < 2; ni++) {
                    mma_f16(acc_g[mi][ni],   af[mi][0], af[mi][1], af[mi][2], af[mi][3],
                            bg0[ni*2], bg0[ni*2+1]);
                    mma_f16(acc_g[mi][2+ni], af[mi][0], af[mi][1], af[mi][2], af[mi][3],
                            bg1[ni*2], bg1[ni*2+1]);
                    mma_f16(acc_u[mi][ni],   af[mi][0], af[mi][1], af[mi][2], af[mi][3],
                            bu0[ni*2], bu0[ni*2+1]);
                    mma_f16(acc_u[mi][2+ni], af[mi][0], af[mi][1], af[mi][2], af[mi][3],
                            bu1[ni*2], bu1[ni*2+1]);
                }
            }
        }

        s ^= 1;
    }

    // epilogue: inter = half( silu(g) * u )
#pragma unroll
    for (int mi = 0; mi < 2; mi++) {
#pragma unroll
        for (int ni = 0; ni < 4; ni++) {
            long r0 = bm + wm*32 + mi*16 + grp;
            long c0 = bn + wn*32 + ni*8 + tig*2;
            float gv, uv; __half2 h;
            gv = acc_g[mi][ni][0]; uv = acc_u[mi][ni][0];
            float o0 = (gv / (1.f + __expf(-gv))) * uv;
            gv = acc_g[mi][ni][1]; uv = acc_u[mi][ni][1];
            float o1 = (gv / (1.f + __expf(-gv))) * uv;
            h = __floats2half2_rn(o0, o1);
            *(__half2*)(inter + r0*INTER + c0) = h;
            gv = acc_g[mi][ni][2]; uv = acc_u[mi][ni][2];
            o0 = (gv / (1.f + __expf(-gv))) * uv;
            gv = acc_g[mi][ni][3]; uv = acc_u[mi][ni][3];
            o1 = (gv / (1.f + __expf(-gv))) * uv;
            h = __floats2half2_rn(o0, o1);
            *(__half2*)(inter + (r0+8)*INTER + c0) = h;
        }
    }
}

// ============================================================================
// Down GEMM fp16 + ldmatrix (unchanged from R7): out = inter * Wd^T, K=5504.
// Block 128x128, warp 64x32; 3 stages x 32KB = 96KB -> 2 CTAs/SM.
// ============================================================================
#define DN_STAGE_B 32768
#define DN_B_OFF   16384
#define DN_SMEM_BYTES (3*DN_STAGE_B)   // 98304

__global__ void __launch_bounds__(256,2)
gemm_down(const __half* __restrict__ A, const __half* __restrict__ B, float* __restrict__ C)
{
    extern __shared__ char smemc[];
    const uint32_t sb = smem_u32(smemc);

    const int tid  = threadIdx.x;
    const int wid  = tid >> 5;
    const int lane = tid & 31;
    const int grp  = lane >> 2;
    const int tig  = lane & 3;
    const int wm   = wid >> 2;
    const int wn   = wid & 3;

    const int NBN = HID/128;   // 16
    const int GM  = 16;
    int bid = blockIdx.x;
    int g   = bid / (GM*NBN);
    int r   = bid % (GM*NBN);
    const long bm = (long)(g*GM + (r % GM)) * 128;
    const int  bn = (r / GM) * 128;

    const int ldr = tid >> 3;
    const int ldc = tid & 7;

    const __half* Ag = A + (bm + ldr)*(long)INTER + ldc*8;
    const __half* Bg = B + (long)(bn + ldr)*INTER + ldc*8;

    float acc[4][4][4];
#pragma unroll
    for (int mi = 0; mi < 4; mi++)
#pragma unroll
        for (int ni = 0; ni < 4; ni++)
#pragma unroll
            for (int q = 0; q < 4; q++) acc[mi][ni][q] = 0.f;

    uint32_t stoff[4];
#pragma unroll
    for (int i = 0; i < 4; i++)
        stoff[i] = SWZB((uint32_t)((ldr + 32*i)*128 + ldc*16));

    const uint32_t swzm = (lane & 7) * 16;
    const uint32_t browA = (wm*64 + (lane & 15)) * 128;
    const uint32_t akbe = ((lane >> 4) & 1) * 16;
    const uint32_t browB = (wn*32 + ((lane >> 4) & 1)*8 + (lane & 7)) * 128;
    const uint32_t bkbe = ((lane >> 3) & 1) * 16;
    uint32_t akb_r[4], bkb_r[4];
#pragma unroll
    for (int ks = 0; ks < 4; ks++) {
        akb_r[ks] = ((uint32_t)(ks*32) + akbe) ^ swzm;
        bkb_r[ks] = ((uint32_t)(ks*32) + bkbe) ^ swzm;
    }

    const int nK = INTER/64;   // 86

#pragma unroll
    for (int p = 0; p < 2; p++) {
        const int k0 = p*64;
        const uint32_t st = sb + p*DN_STAGE_B;
#pragma unroll
        for (int i = 0; i < 4; i++) {
            cpa16(st + stoff[i],            Ag + (long)i*32*INTER + k0);
            cpa16(st + DN_B_OFF + stoff[i], Bg + (long)i*32*INTER + k0);
        }
        CP_COMMIT();
    }

    int s = 0, sl = 2;
    for (int j = 0; j < nK; j++) {
        CP_WAIT(1);
        __syncthreads();

        if (j + 2 < nK) {
            const int k0 = (j+2)*64;
            const uint32_t st = sb + sl*DN_STAGE_B;
#pragma unroll
            for (int i = 0; i < 4; i++) {
                cpa16(st + stoff[i],            Ag + (long)i*32*INTER + k0);
                cpa16(st + DN_B_OFF + stoff[i], Bg + (long)i*32*INTER + k0);
            }
        }
        CP_COMMIT();

        const uint32_t As = sb + s*DN_STAGE_B;
        const uint32_t Bs = As + DN_B_OFF;

#pragma unroll
        for (int ks = 0; ks < 4; ks++) {
            uint32_t af[4][4], bf0[4], bf1[4];
#pragma unroll
            for (int mi = 0; mi < 4; mi++)
                ldsm4(af[mi], As + browA + mi*2048 + akb_r[ks]);
            ldsm4(bf0, Bs + browB + bkb_r[ks]);              // ni 0,1
            ldsm4(bf1, Bs + browB + 16*128 + bkb_r[ks]);     // ni 2,3
#pragma unroll
            for (int mi = 0; mi < 4; mi++) {
#pragma unroll
                for (int ni = 0; ni < 2; ni++)
                    mma_f16(acc[mi][ni], af[mi][0], af[mi][1], af[mi][2], af[mi][3],
                            bf0[ni*2], bf0[ni*2+1]);
#pragma unroll
                for (int ni = 0; ni < 2; ni++)
                    mma_f16(acc[mi][2+ni], af[mi][0], af[mi][1], af[mi][2], af[mi][3],
                            bf1[ni*2], bf1[ni*2+1]);
            }
        }

        s = (s == 2) ? 0 : s + 1;
        sl = (sl == 2) ? 0 : sl + 1;
    }

#pragma unroll
    for (int mi = 0; mi < 4; mi++) {
#pragma unroll
        for (int ni = 0; ni < 4; ni++) {
            long r0 = bm + wm*64 + mi*16 + grp;
            long c0 = bn + wn*32 + ni*8 + tig*2;
            *(float2*)(C + r0*HID + c0)     = make_float2(acc[mi][ni][0], acc[mi][ni][1]);
            *(float2*)(C + (r0+8)*HID + c0) = make_float2(acc[mi][ni][2], acc[mi][ni][3]);
        }
    }
}

// ---------------- elementwise / reductions ----------------
__global__ void cvt_h_kernel(const float4* __restrict__ in, __half2* __restrict__ out, long n4){
    long i = (long)blockIdx.x * blockDim.x + threadIdx.x;
    if (i >= n4) return;
    float4 v = in[i];
    out[2*i]   = __floats2half2_rn(v.x, v.y);
    out[2*i+1] = __floats2half2_rn(v.z, v.w);
}

__global__ void rowsq_kernel(const float* __restrict__ wup, float* __restrict__ out){
    int row  = blockIdx.x * 8 + (threadIdx.x >> 5);
    int lane = threadIdx.x & 31;
    if (row >= INTER) return;
    const float4* p = (const float4*)(wup + (long)row * HID);
    float s = 0.f;
#pragma unroll 4
    for (int j = lane; j < HID/4; j += 32) {
        float4 v = p[j];
        s += v.x*v.x + v.y*v.y + v.z*v.z + v.w*v.w;
    }
#pragma unroll
    for (int off = 16; off > 0; off >>= 1) s += __shfl_xor_sync(0xffffffffu, s, off);
    if (lane == 0) out[row] = s;
}

__global__ void impacts_p1(const __half* __restrict__ inter, float* __restrict__ part){
    int i = blockIdx.x * 256 + threadIdx.x;
    int sc = blockIdx.y;
    if (i >= INTER) return;
    const __half* p = inter + (long)sc * 256 * INTER + i;
    float s = 0.f;
#pragma unroll 8
    for (int rr = 0; rr < 256; rr++) { float v = __half2float(p[(long)rr * INTER]); s += v*v; }
    part[(long)sc * INTER + i] = s;
}

__global__ void impacts_p2(const float* __restrict__ part, const float* __restrict__ rowsq,
                           float* __restrict__ out){
    int idx = blockIdx.x * 256 + threadIdx.x;
    if (idx >= BATCH * INTER) return;
    int b = idx / INTER, i = idx - b * INTER;
    float s = 0.f;
#pragma unroll
    for (int k = 0; k < 8; k++) s += part[(long)(b*8 + k) * INTER + i];
    out[idx] = sqrtf(s * rowsq[i]);
}

// ---------------- launch ----------------
extern "C" void kernel_launch(void* const* d_in, const int* in_sizes, int n_in,
                              void* d_out, int out_size)
{
    const float* X  = (const float*)d_in[0];
    const float* Wg = (const float*)d_in[1];
    const float* Wu = (const float*)d_in[2];
    const float* Wd = (const float*)d_in[3];
    float* out = (float*)d_out;

    __half *Xh, *Wgh, *Wuh, *Wdh, *inter;
    float *rsq, *part;
    cudaGetSymbolAddress((void**)&Xh,  g_Xh);
    cudaGetSymbolAddress((void**)&Wgh, g_Wgh);
    cudaGetSymbolAddress((void**)&Wuh, g_Wuh);
    cudaGetSymbolAddress((void**)&Wdh, g_Wdh);
    cudaGetSymbolAddress((void**)&inter, g_inter);
    cudaGetSymbolAddress((void**)&rsq, g_rowsq);
    cudaGetSymbolAddress((void**)&part, g_part);

    cudaFuncSetAttribute(gemm_gu,   cudaFuncAttributeMaxDynamicSharedMemorySize, GU_SMEM_BYTES);
    cudaFuncSetAttribute(gemm_down, cudaFuncAttributeMaxDynamicSharedMemorySize, DN_SMEM_BYTES);

    long nX = (long)MTOK * HID / 4, nW = (long)INTER * HID / 4;

    cvt_h_kernel<<<(unsigned)((nX + 255)/256), 256>>>((const float4*)X,  (__half2*)Xh,  nX);
    cvt_h_kernel<<<(unsigned)((nW + 255)/256), 256>>>((const float4*)Wg, (__half2*)Wgh, nW);
    cvt_h_kernel<<<(unsigned)((nW + 255)/256), 256>>>((const float4*)Wu, (__half2*)Wuh, nW);

    // launch 4 (ncu capture target)
    gemm_gu<<<(INTER/128)*(MTOK/128), 512, GU_SMEM_BYTES>>>(Xh, Wgh, Wuh, inter);

    cvt_h_kernel<<<(unsigned)((nW + 255)/256), 256>>>((const float4*)Wd, (__half2*)Wdh, nW);

    rowsq_kernel<<<(INTER + 7)/8, 256>>>(Wu, rsq);
    dim3 gp1((INTER + 255)/256, 32);
    impacts_p1<<<gp1, 256>>>(inter, part);
    impacts_p2<<<(BATCH*INTER + 255)/256, 256>>>(part, rsq, out + OUT_ELEMS);

    gemm_down<<<(HID/128)*(MTOK/128), 256, DN_SMEM_BYTES>>>(inter, Wdh, out);
}

// round 9
// speedup vs baseline: 1.1526x; 1.1526x over previous
#include <cuda_runtime.h>
#include <cuda_fp16.h>
#include <cstdint>
#include <math.h>

#define BATCH 4
#define SEQ   2048
#define HID   2048
#define INTER 5504
#define MTOK  (BATCH*SEQ)            // 8192
#define OUT_ELEMS ((long)MTOK*HID)   // 16777216

// ---------------- scratch ----------------
__device__ __half g_Xh [(long)MTOK*HID];
__device__ __half g_Wgh[(long)INTER*HID];
__device__ __half g_Wuh[(long)INTER*HID];
__device__ __half g_Wdh[(long)HID*INTER];
__device__ __half g_inter[(long)MTOK*INTER];
__device__ float  g_rowsq[INTER];
__device__ float  g_part [32L*INTER];

// ---------------- helpers ----------------
__device__ __forceinline__ uint32_t smem_u32(const void* p){
    uint32_t a;
    asm("{ .reg .u64 t; cvta.to.shared.u64 t, %1; cvt.u32.u64 %0, t; }" : "=r"(a) : "l"(p));
    return a;
}
__device__ __forceinline__ void cpa16(uint32_t dst, const void* src){
    asm volatile("cp.async.cg.shared.global [%0], [%1], 16;" :: "r"(dst), "l"(src));
}
__device__ __forceinline__ void ldsm4(uint32_t r[4], uint32_t addr){
    asm volatile("ldmatrix.sync.aligned.m8n8.x4.shared.b16 {%0,%1,%2,%3}, [%4];"
                 : "=r"(r[0]), "=r"(r[1]), "=r"(r[2]), "=r"(r[3]) : "r"(addr));
}
__device__ __forceinline__ void mma_f16(float c[4],
                                        uint32_t a0, uint32_t a1, uint32_t a2, uint32_t a3,
                                        uint32_t b0, uint32_t b1) {
    asm volatile(
        "mma.sync.aligned.m16n8k16.row.col.f32.f16.f16.f32 "
        "{%0,%1,%2,%3}, {%4,%5,%6,%7}, {%8,%9}, {%0,%1,%2,%3};"
        : "+f"(c[0]), "+f"(c[1]), "+f"(c[2]), "+f"(c[3])
        : "r"(a0), "r"(a1), "r"(a2), "r"(a3), "r"(b0), "r"(b1));
}
#define CP_COMMIT() asm volatile("cp.async.commit_group;" ::: "memory")
#define CP_WAIT(n)  asm volatile("cp.async.wait_group %0;" :: "n"(n) : "memory")

// 128B-row XOR swizzle (conflict-free)
#define SWZB(o) ((o) ^ (((o) >> 3) & 0x70))

// ============================================================================
// Fused gate/up GEMM + SwiGLU, fp16 mma + ldmatrix. Block 128m x 64n.
// 8 warps: wm(2) x wn(4); warp tile 64m x 16n per mat.
// 3 stages x 32KB = 96KB -> 2 CTAs/SM. One barrier per chunk; loads overlap MMA.
// Mainloop unrolled by 3 so stage offsets are compile-time.
// ============================================================================
#define GU_STAGE_B 32768
#define GU_BG_OFF  16384
#define GU_BU_OFF  24576
#define GU_SMEM_BYTES (3*GU_STAGE_B)   // 98304

__global__ void __launch_bounds__(256,2)
gemm_gu(const __half* __restrict__ X, const __half* __restrict__ Wg,
        const __half* __restrict__ Wu, __half* __restrict__ inter)
{
    extern __shared__ char smemc[];
    const uint32_t sb = smem_u32(smemc);

    const int tid  = threadIdx.x;
    const int wid  = tid >> 5;
    const int lane = tid & 31;
    const int grp  = lane >> 2;
    const int tig  = lane & 3;
    const int wm   = wid >> 2;    // 0..1
    const int wn   = wid & 3;     // 0..3

    const int NBN = INTER/64;     // 86
    const int GM  = 16;
    int bid = blockIdx.x;
    int g   = bid / (GM*NBN);
    int r   = bid % (GM*NBN);
    const long bm = (long)(g*GM + (r % GM)) * 128;
    const int  bn = (r / GM) * 64;

    const int ldr = tid >> 3;        // 0..31
    const int ldc = tid & 7;         // 0..7 (16B units)

    const __half* Ag = X  + (bm + ldr)*(long)HID + ldc*8;
    const __half* Gg = Wg + (long)(bn + ldr)*HID + ldc*8;
    const __half* Ug = Wu + (long)(bn + ldr)*HID + ldc*8;

    float acc_g[4][2][4], acc_u[4][2][4];
#pragma unroll
    for (int mi = 0; mi < 4; mi++)
#pragma unroll
        for (int ni = 0; ni < 2; ni++)
#pragma unroll
            for (int q = 0; q < 4; q++) { acc_g[mi][ni][q] = 0.f; acc_u[mi][ni][q] = 0.f; }

    uint32_t stoffA[4];
#pragma unroll
    for (int i = 0; i < 4; i++)
        stoffA[i] = SWZB((uint32_t)((ldr + 32*i)*128 + ldc*16));
    uint32_t stoffB[2];
#pragma unroll
    for (int i = 0; i < 2; i++)
        stoffB[i] = SWZB((uint32_t)((ldr + 32*i)*128 + ldc*16));

    // ldmatrix per-lane geometry (hoisted XOR terms)
    const uint32_t swzm = (lane & 7) * 16;
    const uint32_t browA = (wm*64 + (lane & 15)) * 128;
    const uint32_t akbe = ((lane >> 4) & 1) * 16;
    const uint32_t browB = (wn*16 + ((lane >> 4) & 1)*8 + (lane & 7)) * 128;
    const uint32_t bkbe = ((lane >> 3) & 1) * 16;
    uint32_t akb_r[4], bkb_r[4];
#pragma unroll
    for (int ks = 0; ks < 4; ks++) {
        akb_r[ks] = ((uint32_t)(ks*32) + akbe) ^ swzm;
        bkb_r[ks] = ((uint32_t)(ks*32) + bkbe) ^ swzm;
    }

    const int nK = HID/64;   // 32

    // preload chunks 0,1 into stages 0,1
#pragma unroll
    for (int p = 0; p < 2; p++) {
        const int k0 = p*64;
        const uint32_t st = sb + p*GU_STAGE_B;
#pragma unroll
        for (int i = 0; i < 4; i++)
            cpa16(st + stoffA[i], Ag + (long)i*32*HID + k0);
#pragma unroll
        for (int i = 0; i < 2; i++) {
            cpa16(st + GU_BG_OFF + stoffB[i], Gg + (long)i*32*HID + k0);
            cpa16(st + GU_BU_OFF + stoffB[i], Ug + (long)i*32*HID + k0);
        }
        CP_COMMIT();
    }

#define GU_BODY(SS)                                                            \
    {                                                                          \
        CP_WAIT(1);                                                            \
        __syncthreads();                                                       \
        if (j + 2 < nK) {                                                      \
            const int k0 = (j+2)*64;                                           \
            const uint32_t st = sb + (((SS)+2)%3)*GU_STAGE_B;                  \
            _Pragma("unroll")                                                  \
            for (int i = 0; i < 4; i++)                                        \
                cpa16(st + stoffA[i], Ag + (long)i*32*HID + k0);               \
            _Pragma("unroll")                                                  \
            for (int i = 0; i < 2; i++) {                                      \
                cpa16(st + GU_BG_OFF + stoffB[i], Gg + (long)i*32*HID + k0);   \
                cpa16(st + GU_BU_OFF + stoffB[i], Ug + (long)i*32*HID + k0);   \
            }                                                                  \
        }                                                                      \
        CP_COMMIT();                                                           \
        const uint32_t As = sb + (SS)*GU_STAGE_B;                              \
        const uint32_t Gs = As + GU_BG_OFF;                                    \
        const uint32_t Us = As + GU_BU_OFF;                                    \
        _Pragma("unroll")                                                      \
        for (int ks = 0; ks < 4; ks++) {                                       \
            uint32_t af[4][4], bg[4], bu[4];                                   \
            _Pragma("unroll")                                                  \
            for (int mi = 0; mi < 4; mi++)                                     \
                ldsm4(af[mi], As + browA + mi*2048 + akb_r[ks]);               \
            ldsm4(bg, Gs + browB + bkb_r[ks]);                                 \
            ldsm4(bu, Us + browB + bkb_r[ks]);                                 \
            _Pragma("unroll")                                                  \
            for (int mi = 0; mi < 4; mi++)                                     \
                _Pragma("unroll")                                              \
                for (int ni = 0; ni < 2; ni++) {                               \
                    mma_f16(acc_g[mi][ni], af[mi][0], af[mi][1], af[mi][2],    \
                            af[mi][3], bg[ni*2], bg[ni*2+1]);                  \
                    mma_f16(acc_u[mi][ni], af[mi][0], af[mi][1], af[mi][2],    \
                            af[mi][3], bu[ni*2], bu[ni*2+1]);                  \
                }                                                              \
        }                                                                      \
        j++;                                                                   \
    }

    {
        int j = 0;
        while (j + 3 <= nK) { GU_BODY(0); GU_BODY(1); GU_BODY(2); }
        // nK % 3 == 2 tail (32 = 3*10 + 2), enters with j % 3 == 0
        GU_BODY(0); GU_BODY(1);
    }
#undef GU_BODY

    // epilogue: inter = half( silu(g) * u )
#pragma unroll
    for (int mi = 0; mi < 4; mi++) {
#pragma unroll
        for (int ni = 0; ni < 2; ni++) {
            long r0 = bm + wm*64 + mi*16 + grp;
            long c0 = bn + wn*16 + ni*8 + tig*2;
            float gv, uv; __half2 h;
            gv = acc_g[mi][ni][0]; uv = acc_u[mi][ni][0];
            float o0 = (gv / (1.f + __expf(-gv))) * uv;
            gv = acc_g[mi][ni][1]; uv = acc_u[mi][ni][1];
            float o1 = (gv / (1.f + __expf(-gv))) * uv;
            h = __floats2half2_rn(o0, o1);
            *(__half2*)(inter + r0*INTER + c0) = h;
            gv = acc_g[mi][ni][2]; uv = acc_u[mi][ni][2];
            o0 = (gv / (1.f + __expf(-gv))) * uv;
            gv = acc_g[mi][ni][3]; uv = acc_u[mi][ni][3];
            o1 = (gv / (1.f + __expf(-gv))) * uv;
            h = __floats2half2_rn(o0, o1);
            *(__half2*)(inter + (r0+8)*INTER + c0) = h;
        }
    }
}

// ============================================================================
// Down GEMM fp16 + ldmatrix: out = inter * Wd^T, K=5504. Block 128x128, warp 64x32.
// 3 stages x 32KB = 96KB -> 2 CTAs/SM. Mainloop unrolled by 3.
// ============================================================================
#define DN_STAGE_B 32768
#define DN_B_OFF   16384
#define DN_SMEM_BYTES (3*DN_STAGE_B)   // 98304

__global__ void __launch_bounds__(256,2)
gemm_down(const __half* __restrict__ A, const __half* __restrict__ B, float* __restrict__ C)
{
    extern __shared__ char smemc[];
    const uint32_t sb = smem_u32(smemc);

    const int tid  = threadIdx.x;
    const int wid  = tid >> 5;
    const int lane = tid & 31;
    const int grp  = lane >> 2;
    const int tig  = lane & 3;
    const int wm   = wid >> 2;
    const int wn   = wid & 3;

    const int NBN = HID/128;   // 16
    const int GM  = 16;
    int bid = blockIdx.x;
    int g   = bid / (GM*NBN);
    int r   = bid % (GM*NBN);
    const long bm = (long)(g*GM + (r % GM)) * 128;
    const int  bn = (r / GM) * 128;

    const int ldr = tid >> 3;
    const int ldc = tid & 7;

    const __half* Ag = A + (bm + ldr)*(long)INTER + ldc*8;
    const __half* Bg = B + (long)(bn + ldr)*INTER + ldc*8;

    float acc[4][4][4];
#pragma unroll
    for (int mi = 0; mi < 4; mi++)
#pragma unroll
        for (int ni = 0; ni < 4; ni++)
#pragma unroll
            for (int q = 0; q < 4; q++) acc[mi][ni][q] = 0.f;

    uint32_t stoff[4];
#pragma unroll
    for (int i = 0; i < 4; i++)
        stoff[i] = SWZB((uint32_t)((ldr + 32*i)*128 + ldc*16));

    const uint32_t swzm = (lane & 7) * 16;
    const uint32_t browA = (wm*64 + (lane & 15)) * 128;
    const uint32_t akbe = ((lane >> 4) & 1) * 16;
    const uint32_t browB = (wn*32 + ((lane >> 4) & 1)*8 + (lane & 7)) * 128;
    const uint32_t bkbe = ((lane >> 3) & 1) * 16;
    uint32_t akb_r[4], bkb_r[4];
#pragma unroll
    for (int ks = 0; ks < 4; ks++) {
        akb_r[ks] = ((uint32_t)(ks*32) + akbe) ^ swzm;
        bkb_r[ks] = ((uint32_t)(ks*32) + bkbe) ^ swzm;
    }

    const int nK = INTER/64;   // 86

#pragma unroll
    for (int p = 0; p < 2; p++) {
        const int k0 = p*64;
        const uint32_t st = sb + p*DN_STAGE_B;
#pragma unroll
        for (int i = 0; i < 4; i++) {
            cpa16(st + stoff[i],            Ag + (long)i*32*INTER + k0);
            cpa16(st + DN_B_OFF + stoff[i], Bg + (long)i*32*INTER + k0);
        }
        CP_COMMIT();
    }

#define DN_BODY(SS)                                                            \
    {                                                                          \
        CP_WAIT(1);                                                            \
        __syncthreads();                                                       \
        if (j + 2 < nK) {                                                      \
            const int k0 = (j+2)*64;                                           \
            const uint32_t st = sb + (((SS)+2)%3)*DN_STAGE_B;                  \
            _Pragma("unroll")                                                  \
            for (int i = 0; i < 4; i++) {                                      \
                cpa16(st + stoff[i],            Ag + (long)i*32*INTER + k0);   \
                cpa16(st + DN_B_OFF + stoff[i], Bg + (long)i*32*INTER + k0);   \
            }                                                                  \
        }                                                                      \
        CP_COMMIT();                                                           \
        const uint32_t As = sb + (SS)*DN_STAGE_B;                              \
        const uint32_t Bs = As + DN_B_OFF;                                     \
        _Pragma("unroll")                                                      \
        for (int ks = 0; ks < 4; ks++) {                                       \
            uint32_t af[4][4], bf0[4], bf1[4];                                 \
            _Pragma("unroll")                                                  \
            for (int mi = 0; mi < 4; mi++)                                     \
                ldsm4(af[mi], As + browA + mi*2048 + akb_r[ks]);               \
            ldsm4(bf0, Bs + browB + bkb_r[ks]);                                \
            ldsm4(bf1, Bs + browB + 16*128 + bkb_r[ks]);                       \
            _Pragma("unroll")                                                  \
            for (int mi = 0; mi < 4; mi++) {                                   \
                _Pragma("unroll")                                              \
                for (int ni = 0; ni < 2; ni++)                                 \
                    mma_f16(acc[mi][ni], af[mi][0], af[mi][1], af[mi][2],      \
                            af[mi][3], bf0[ni*2], bf0[ni*2+1]);                \
                _Pragma("unroll")                                              \
                for (int ni = 0; ni < 2; ni++)                                 \
                    mma_f16(acc[mi][2+ni], af[mi][0], af[mi][1], af[mi][2],    \
                            af[mi][3], bf1[ni*2], bf1[ni*2+1]);                \
            }                                                                  \
        }                                                                      \
        j++;                                                                   \
    }

    {
        int j = 0;
        while (j + 3 <= nK) { DN_BODY(0); DN_BODY(1); DN_BODY(2); }
        // nK % 3 == 2 tail (86 = 3*28 + 2), enters with j % 3 == 0
        DN_BODY(0); DN_BODY(1);
    }
#undef DN_BODY

#pragma unroll
    for (int mi = 0; mi < 4; mi++) {
#pragma unroll
        for (int ni = 0; ni < 4; ni++) {
            long r0 = bm + wm*64 + mi*16 + grp;
            long c0 = bn + wn*32 + ni*8 + tig*2;
            *(float2*)(C + r0*HID + c0)     = make_float2(acc[mi][ni][0], acc[mi][ni][1]);
            *(float2*)(C + (r0+8)*HID + c0) = make_float2(acc[mi][ni][2], acc[mi][ni][3]);
        }
    }
}

// ---------------- elementwise / reductions ----------------
__global__ void cvt_h_kernel(const float4* __restrict__ in, __half2* __restrict__ out, long n4){
    long i = (long)blockIdx.x * blockDim.x + threadIdx.x;
    if (i >= n4) return;
    float4 v = in[i];
    out[2*i]   = __floats2half2_rn(v.x, v.y);
    out[2*i+1] = __floats2half2_rn(v.z, v.w);
}

__global__ void rowsq_kernel(const float* __restrict__ wup, float* __restrict__ out){
    int row  = blockIdx.x * 8 + (threadIdx.x >> 5);
    int lane = threadIdx.x & 31;
    if (row >= INTER) return;
    const float4* p = (const float4*)(wup + (long)row * HID);
    float s = 0.f;
#pragma unroll 4
    for (int j = lane; j < HID/4; j += 32) {
        float4 v = p[j];
        s += v.x*v.x + v.y*v.y + v.z*v.z + v.w*v.w;
    }
#pragma unroll
    for (int off = 16; off > 0; off >>= 1) s += __shfl_xor_sync(0xffffffffu, s, off);
    if (lane == 0) out[row] = s;
}

__global__ void impacts_p1(const __half* __restrict__ inter, float* __restrict__ part){
    int i = blockIdx.x * 256 + threadIdx.x;
    int sc = blockIdx.y;
    if (i >= INTER) return;
    const __half* p = inter + (long)sc * 256 * INTER + i;
    float s = 0.f;
#pragma unroll 8
    for (int rr = 0; rr < 256; rr++) { float v = __half2float(p[(long)rr * INTER]); s += v*v; }
    part[(long)sc * INTER + i] = s;
}

__global__ void impacts_p2(const float* __restrict__ part, const float* __restrict__ rowsq,
                           float* __restrict__ out){
    int idx = blockIdx.x * 256 + threadIdx.x;
    if (idx >= BATCH * INTER) return;
    int b = idx / INTER, i = idx - b * INTER;
    float s = 0.f;
#pragma unroll
    for (int k = 0; k < 8; k++) s += part[(long)(b*8 + k) * INTER + i];
    out[idx] = sqrtf(s * rowsq[i]);
}

// ---------------- launch ----------------
extern "C" void kernel_launch(void* const* d_in, const int* in_sizes, int n_in,
                              void* d_out, int out_size)
{
    const float* X  = (const float*)d_in[0];
    const float* Wg = (const float*)d_in[1];
    const float* Wu = (const float*)d_in[2];
    const float* Wd = (const float*)d_in[3];
    float* out = (float*)d_out;

    __half *Xh, *Wgh, *Wuh, *Wdh, *inter;
    float *rsq, *part;
    cudaGetSymbolAddress((void**)&Xh,  g_Xh);
    cudaGetSymbolAddress((void**)&Wgh, g_Wgh);
    cudaGetSymbolAddress((void**)&Wuh, g_Wuh);
    cudaGetSymbolAddress((void**)&Wdh, g_Wdh);
    cudaGetSymbolAddress((void**)&inter, g_inter);
    cudaGetSymbolAddress((void**)&rsq, g_rowsq);
    cudaGetSymbolAddress((void**)&part, g_part);

    cudaFuncSetAttribute(gemm_gu,   cudaFuncAttributeMaxDynamicSharedMemorySize, GU_SMEM_BYTES);
    cudaFuncSetAttribute(gemm_down, cudaFuncAttributeMaxDynamicSharedMemorySize, DN_SMEM_BYTES);

    long nX = (long)MTOK * HID / 4, nW = (long)INTER * HID / 4;

    cvt_h_kernel<<<(unsigned)((nX + 255)/256), 256>>>((const float4*)X,  (__half2*)Xh,  nX);
    cvt_h_kernel<<<(unsigned)((nW + 255)/256), 256>>>((const float4*)Wg, (__half2*)Wgh, nW);
    cvt_h_kernel<<<(unsigned)((nW + 255)/256), 256>>>((const float4*)Wu, (__half2*)Wuh, nW);

    // launch 4 (ncu capture target)
    gemm_gu<<<(INTER/64)*(MTOK/128), 256, GU_SMEM_BYTES>>>(Xh, Wgh, Wuh, inter);

    cvt_h_kernel<<<(unsigned)((nW + 255)/256), 256>>>((const float4*)Wd, (__half2*)Wdh, nW);

    rowsq_kernel<<<(INTER + 7)/8, 256>>>(Wu, rsq);
    dim3 gp1((INTER + 255)/256, 32);
    impacts_p1<<<gp1, 256>>>(inter, part);
    impacts_p2<<<(BATCH*INTER + 255)/256, 256>>>(part, rsq, out + OUT_ELEMS);

    gemm_down<<<(HID/128)*(MTOK/128), 256, DN_SMEM_BYTES>>>(inter, Wdh, out);
}

// round 10
// speedup vs baseline: 1.1632x; 1.0092x over previous
#include <cuda_runtime.h>
#include <cuda_fp16.h>
#include <cstdint>
#include <math.h>

#define BATCH 4
#define SEQ   2048
#define HID   2048
#define INTER 5504
#define MTOK  (BATCH*SEQ)            // 8192
#define OUT_ELEMS ((long)MTOK*HID)   // 16777216

// ---------------- scratch ----------------
__device__ __half g_Xh [(long)MTOK*HID];
__device__ __half g_Wgh[(long)INTER*HID];
__device__ __half g_Wuh[(long)INTER*HID];
__device__ __half g_Wdh[(long)HID*INTER];
__device__ __half g_inter[(long)MTOK*INTER];
__device__ float  g_rowsq[INTER];
__device__ float  g_s[BATCH*INTER];      // impacts accumulator (atomicAdd)

// ---------------- helpers ----------------
__device__ __forceinline__ uint32_t smem_u32(const void* p){
    uint32_t a;
    asm("{ .reg .u64 t; cvta.to.shared.u64 t, %1; cvt.u32.u64 %0, t; }" : "=r"(a) : "l"(p));
    return a;
}
__device__ __forceinline__ void cpa16(uint32_t dst, const void* src){
    asm volatile("cp.async.cg.shared.global [%0], [%1], 16;" :: "r"(dst), "l"(src));
}
__device__ __forceinline__ void ldsm4(uint32_t r[4], uint32_t addr){
    asm volatile("ldmatrix.sync.aligned.m8n8.x4.shared.b16 {%0,%1,%2,%3}, [%4];"
                 : "=r"(r[0]), "=r"(r[1]), "=r"(r[2]), "=r"(r[3]) : "r"(addr));
}
__device__ __forceinline__ void mma_f16(float c[4],
                                        uint32_t a0, uint32_t a1, uint32_t a2, uint32_t a3,
                                        uint32_t b0, uint32_t b1) {
    asm volatile(
        "mma.sync.aligned.m16n8k16.row.col.f32.f16.f16.f32 "
        "{%0,%1,%2,%3}, {%4,%5,%6,%7}, {%8,%9}, {%0,%1,%2,%3};"
        : "+f"(c[0]), "+f"(c[1]), "+f"(c[2]), "+f"(c[3])
        : "r"(a0), "r"(a1), "r"(a2), "r"(a3), "r"(b0), "r"(b1));
}
#define CP_COMMIT() asm volatile("cp.async.commit_group;" ::: "memory")
#define CP_WAIT(n)  asm volatile("cp.async.wait_group %0;" :: "n"(n) : "memory")

// 128B-row XOR swizzle (conflict-free)
#define SWZB(o) ((o) ^ (((o) >> 3) & 0x70))

// ============================================================================
// Fused gate/up GEMM + SwiGLU + impacts partial reduction.
// Block 128m x 64n, 8 warps (2m x 4n), warp 64m x 16n per mat.
// 3 stages x 32KB = 96KB -> 2 CTAs/SM. Mainloop unrolled by 3.
// ============================================================================
#define GU_STAGE_B 32768
#define GU_BG_OFF  16384
#define GU_BU_OFF  24576
#define GU_SMEM_BYTES (3*GU_STAGE_B)   // 98304

__global__ void __launch_bounds__(256,2)
gemm_gu(const __half* __restrict__ X, const __half* __restrict__ Wg,
        const __half* __restrict__ Wu, __half* __restrict__ inter,
        float* __restrict__ spart)
{
    extern __shared__ char smemc[];
    const uint32_t sb = smem_u32(smemc);

    const int tid  = threadIdx.x;
    const int wid  = tid >> 5;
    const int lane = tid & 31;
    const int grp  = lane >> 2;
    const int tig  = lane & 3;
    const int wm   = wid >> 2;    // 0..1
    const int wn   = wid & 3;     // 0..3

    const int NBN = INTER/64;     // 86
    const int GM  = 16;
    int bid = blockIdx.x;
    int g   = bid / (GM*NBN);
    int r   = bid % (GM*NBN);
    const long bm = (long)(g*GM + (r % GM)) * 128;
    const int  bn = (r / GM) * 64;

    const int ldr = tid >> 3;        // 0..31
    const int ldc = tid & 7;         // 0..7 (16B units)

    const __half* Ag = X  + (bm + ldr)*(long)HID + ldc*8;
    const __half* Gg = Wg + (long)(bn + ldr)*HID + ldc*8;
    const __half* Ug = Wu + (long)(bn + ldr)*HID + ldc*8;

    float acc_g[4][2][4], acc_u[4][2][4];
#pragma unroll
    for (int mi = 0; mi < 4; mi++)
#pragma unroll
        for (int ni = 0; ni < 2; ni++)
#pragma unroll
            for (int q = 0; q < 4; q++) { acc_g[mi][ni][q] = 0.f; acc_u[mi][ni][q] = 0.f; }

    uint32_t stoffA[4];
#pragma unroll
    for (int i = 0; i < 4; i++)
        stoffA[i] = SWZB((uint32_t)((ldr + 32*i)*128 + ldc*16));
    uint32_t stoffB[2];
#pragma unroll
    for (int i = 0; i < 2; i++)
        stoffB[i] = SWZB((uint32_t)((ldr + 32*i)*128 + ldc*16));

    // ldmatrix per-lane geometry (hoisted XOR terms)
    const uint32_t swzm = (lane & 7) * 16;
    const uint32_t browA = (wm*64 + (lane & 15)) * 128;
    const uint32_t akbe = ((lane >> 4) & 1) * 16;
    const uint32_t browB = (wn*16 + ((lane >> 4) & 1)*8 + (lane & 7)) * 128;
    const uint32_t bkbe = ((lane >> 3) & 1) * 16;
    uint32_t akb_r[4], bkb_r[4];
#pragma unroll
    for (int ks = 0; ks < 4; ks++) {
        akb_r[ks] = ((uint32_t)(ks*32) + akbe) ^ swzm;
        bkb_r[ks] = ((uint32_t)(ks*32) + bkbe) ^ swzm;
    }

    const int nK = HID/64;   // 32

    // preload chunks 0,1 into stages 0,1
#pragma unroll
    for (int p = 0; p < 2; p++) {
        const int k0 = p*64;
        const uint32_t st = sb + p*GU_STAGE_B;
#pragma unroll
        for (int i = 0; i < 4; i++)
            cpa16(st + stoffA[i], Ag + (long)i*32*HID + k0);
#pragma unroll
        for (int i = 0; i < 2; i++) {
            cpa16(st + GU_BG_OFF + stoffB[i], Gg + (long)i*32*HID + k0);
            cpa16(st + GU_BU_OFF + stoffB[i], Ug + (long)i*32*HID + k0);
        }
        CP_COMMIT();
    }

#define GU_BODY(SS)                                                            \
    {                                                                          \
        CP_WAIT(1);                                                            \
        __syncthreads();                                                       \
        if (j + 2 < nK) {                                                      \
            const int k0 = (j+2)*64;                                           \
            const uint32_t st = sb + (((SS)+2)%3)*GU_STAGE_B;                  \
            _Pragma("unroll")                                                  \
            for (int i = 0; i < 4; i++)                                        \
                cpa16(st + stoffA[i], Ag + (long)i*32*HID + k0);               \
            _Pragma("unroll")                                                  \
            for (int i = 0; i < 2; i++) {                                      \
                cpa16(st + GU_BG_OFF + stoffB[i], Gg + (long)i*32*HID + k0);   \
                cpa16(st + GU_BU_OFF + stoffB[i], Ug + (long)i*32*HID + k0);   \
            }                                                                  \
        }                                                                      \
        CP_COMMIT();                                                           \
        const uint32_t As = sb + (SS)*GU_STAGE_B;                              \
        const uint32_t Gs = As + GU_BG_OFF;                                    \
        const uint32_t Us = As + GU_BU_OFF;                                    \
        _Pragma("unroll")                                                      \
        for (int ks = 0; ks < 4; ks++) {                                       \
            uint32_t af[4][4], bg[4], bu[4];                                   \
            _Pragma("unroll")                                                  \
            for (int mi = 0; mi < 4; mi++)                                     \
                ldsm4(af[mi], As + browA + mi*2048 + akb_r[ks]);               \
            ldsm4(bg, Gs + browB + bkb_r[ks]);                                 \
            ldsm4(bu, Us + browB + bkb_r[ks]);                                 \
            _Pragma("unroll")                                                  \
            for (int mi = 0; mi < 4; mi++)                                     \
                _Pragma("unroll")                                              \
                for (int ni = 0; ni < 2; ni++) {                               \
                    mma_f16(acc_g[mi][ni], af[mi][0], af[mi][1], af[mi][2],    \
                            af[mi][3], bg[ni*2], bg[ni*2+1]);                  \
                    mma_f16(acc_u[mi][ni], af[mi][0], af[mi][1], af[mi][2],    \
                            af[mi][3], bu[ni*2], bu[ni*2+1]);                  \
                }                                                              \
        }                                                                      \
        j++;                                                                   \
    }

    {
        int j = 0;
        while (j + 3 <= nK) { GU_BODY(0); GU_BODY(1); GU_BODY(2); }
        // nK % 3 == 2 tail (32 = 3*10 + 2), enters with j % 3 == 0
        GU_BODY(0); GU_BODY(1);
    }
#undef GU_BODY

    // epilogue: inter = half( silu(g) * u );  colsum += o^2 for impacts
    float cs[2][2] = {{0.f,0.f},{0.f,0.f}};   // [ni][col in pair]
#pragma unroll
    for (int mi = 0; mi < 4; mi++) {
#pragma unroll
        for (int ni = 0; ni < 2; ni++) {
            long r0 = bm + wm*64 + mi*16 + grp;
            long c0 = bn + wn*16 + ni*8 + tig*2;
            float gv, uv; __half2 h;
            gv = acc_g[mi][ni][0]; uv = acc_u[mi][ni][0];
            float o0 = (gv / (1.f + __expf(-gv))) * uv;
            gv = acc_g[mi][ni][1]; uv = acc_u[mi][ni][1];
            float o1 = (gv / (1.f + __expf(-gv))) * uv;
            h = __floats2half2_rn(o0, o1);
            *(__half2*)(inter + r0*INTER + c0) = h;
            gv = acc_g[mi][ni][2]; uv = acc_u[mi][ni][2];
            float o2 = (gv / (1.f + __expf(-gv))) * uv;
            gv = acc_g[mi][ni][3]; uv = acc_u[mi][ni][3];
            float o3 = (gv / (1.f + __expf(-gv))) * uv;
            h = __floats2half2_rn(o2, o3);
            *(__half2*)(inter + (r0+8)*INTER + c0) = h;
            cs[ni][0] += o0*o0 + o2*o2;
            cs[ni][1] += o1*o1 + o3*o3;
        }
    }
    // reduce over the 8 row-lane-groups (lanes differing in bits 2..4)
#pragma unroll
    for (int off = 4; off < 32; off <<= 1) {
#pragma unroll
        for (int ni = 0; ni < 2; ni++) {
            cs[ni][0] += __shfl_xor_sync(0xffffffffu, cs[ni][0], off);
            cs[ni][1] += __shfl_xor_sync(0xffffffffu, cs[ni][1], off);
        }
    }
    if (grp == 0) {
        const int b = (int)(bm >> 11);          // bm / SEQ
        float* sp = spart + b*INTER;
#pragma unroll
        for (int ni = 0; ni < 2; ni++) {
            int c0 = bn + wn*16 + ni*8 + tig*2;
            atomicAdd(&sp[c0],   cs[ni][0]);
            atomicAdd(&sp[c0+1], cs[ni][1]);
        }
    }
}

// ============================================================================
// Down GEMM fp16 + ldmatrix: out = inter * Wd^T, K=5504. Block 128x128, warp 64x32.
// 3 stages x 32KB = 96KB -> 2 CTAs/SM. Mainloop unrolled by 3.
// ============================================================================
#define DN_STAGE_B 32768
#define DN_B_OFF   16384
#define DN_SMEM_BYTES (3*DN_STAGE_B)   // 98304

__global__ void __launch_bounds__(256,2)
gemm_down(const __half* __restrict__ A, const __half* __restrict__ B, float* __restrict__ C)
{
    extern __shared__ char smemc[];
    const uint32_t sb = smem_u32(smemc);

    const int tid  = threadIdx.x;
    const int wid  = tid >> 5;
    const int lane = tid & 31;
    const int grp  = lane >> 2;
    const int tig  = lane & 3;
    const int wm   = wid >> 2;
    const int wn   = wid & 3;

    const int NBN = HID/128;   // 16
    const int GM  = 16;
    int bid = blockIdx.x;
    int g   = bid / (GM*NBN);
    int r   = bid % (GM*NBN);
    const long bm = (long)(g*GM + (r % GM)) * 128;
    const int  bn = (r / GM) * 128;

    const int ldr = tid >> 3;
    const int ldc = tid & 7;

    const __half* Ag = A + (bm + ldr)*(long)INTER + ldc*8;
    const __half* Bg = B + (long)(bn + ldr)*INTER + ldc*8;

    float acc[4][4][4];
#pragma unroll
    for (int mi = 0; mi < 4; mi++)
#pragma unroll
        for (int ni = 0; ni < 4; ni++)
#pragma unroll
            for (int q = 0; q < 4; q++) acc[mi][ni][q] = 0.f;

    uint32_t stoff[4];
#pragma unroll
    for (int i = 0; i < 4; i++)
        stoff[i] = SWZB((uint32_t)((ldr + 32*i)*128 + ldc*16));

    const uint32_t swzm = (lane & 7) * 16;
    const uint32_t browA = (wm*64 + (lane & 15)) * 128;
    const uint32_t akbe = ((lane >> 4) & 1) * 16;
    const uint32_t browB = (wn*32 + ((lane >> 4) & 1)*8 + (lane & 7)) * 128;
    const uint32_t bkbe = ((lane >> 3) & 1) * 16;
    uint32_t akb_r[4], bkb_r[4];
#pragma unroll
    for (int ks = 0; ks < 4; ks++) {
        akb_r[ks] = ((uint32_t)(ks*32) + akbe) ^ swzm;
        bkb_r[ks] = ((uint32_t)(ks*32) + bkbe) ^ swzm;
    }

    const int nK = INTER/64;   // 86

#pragma unroll
    for (int p = 0; p < 2; p++) {
        const int k0 = p*64;
        const uint32_t st = sb + p*DN_STAGE_B;
#pragma unroll
        for (int i = 0; i < 4; i++) {
            cpa16(st + stoff[i],            Ag + (long)i*32*INTER + k0);
            cpa16(st + DN_B_OFF + stoff[i], Bg + (long)i*32*INTER + k0);
        }
        CP_COMMIT();
    }

#define DN_BODY(SS)                                                            \
    {                                                                          \
        CP_WAIT(1);                                                            \
        __syncthreads();                                                       \
        if (j + 2 < nK) {                                                      \
            const int k0 = (j+2)*64;                                           \
            const uint32_t st = sb + (((SS)+2)%3)*DN_STAGE_B;                  \
            _Pragma("unroll")                                                  \
            for (int i = 0; i < 4; i++) {                                      \
                cpa16(st + stoff[i],            Ag + (long)i*32*INTER + k0);   \
                cpa16(st + DN_B_OFF + stoff[i], Bg + (long)i*32*INTER + k0);   \
            }                                                                  \
        }                                                                      \
        CP_COMMIT();                                                           \
        const uint32_t As = sb + (SS)*DN_STAGE_B;                              \
        const uint32_t Bs = As + DN_B_OFF;                                     \
        _Pragma("unroll")                                                      \
        for (int ks = 0; ks < 4; ks++) {                                       \
            uint32_t af[4][4], bf0[4], bf1[4];                                 \
            _Pragma("unroll")                                                  \
            for (int mi = 0; mi < 4; mi++)                                     \
                ldsm4(af[mi], As + browA + mi*2048 + akb_r[ks]);               \
            ldsm4(bf0, Bs + browB + bkb_r[ks]);                                \
            ldsm4(bf1, Bs + browB + 16*128 + bkb_r[ks]);                       \
            _Pragma("unroll")                                                  \
            for (int mi = 0; mi < 4; mi++) {                                   \
                _Pragma("unroll")                                              \
                for (int ni = 0; ni < 2; ni++)                                 \
                    mma_f16(acc[mi][ni], af[mi][0], af[mi][1], af[mi][2],      \
                            af[mi][3], bf0[ni*2], bf0[ni*2+1]);                \
                _Pragma("unroll")                                              \
                for (int ni = 0; ni < 2; ni++)                                 \
                    mma_f16(acc[mi][2+ni], af[mi][0], af[mi][1], af[mi][2],    \
                            af[mi][3], bf1[ni*2], bf1[ni*2+1]);                \
            }                                                                  \
        }                                                                      \
        j++;                                                                   \
    }

    {
        int j = 0;
        while (j + 3 <= nK) { DN_BODY(0); DN_BODY(1); DN_BODY(2); }
        // nK % 3 == 2 tail (86 = 3*28 + 2), enters with j % 3 == 0
        DN_BODY(0); DN_BODY(1);
    }
#undef DN_BODY

#pragma unroll
    for (int mi = 0; mi < 4; mi++) {
#pragma unroll
        for (int ni = 0; ni < 4; ni++) {
            long r0 = bm + wm*64 + mi*16 + grp;
            long c0 = bn + wn*32 + ni*8 + tig*2;
            *(float2*)(C + r0*HID + c0)     = make_float2(acc[mi][ni][0], acc[mi][ni][1]);
            *(float2*)(C + (r0+8)*HID + c0) = make_float2(acc[mi][ni][2], acc[mi][ni][3]);
        }
    }
}

// ---------------- elementwise / reductions ----------------
__global__ void cvt_h_kernel(const float4* __restrict__ in, __half2* __restrict__ out, long n4){
    long i = (long)blockIdx.x * blockDim.x + threadIdx.x;
    if (i >= n4) return;
    float4 v = in[i];
    out[2*i]   = __floats2half2_rn(v.x, v.y);
    out[2*i+1] = __floats2half2_rn(v.z, v.w);
}

__global__ void rowsq_kernel(const float* __restrict__ wup, float* __restrict__ out){
    int row  = blockIdx.x * 8 + (threadIdx.x >> 5);
    int lane = threadIdx.x & 31;
    if (row >= INTER) return;
    const float4* p = (const float4*)(wup + (long)row * HID);
    float s = 0.f;
#pragma unroll 4
    for (int j = lane; j < HID/4; j += 32) {
        float4 v = p[j];
        s += v.x*v.x + v.y*v.y + v.z*v.z + v.w*v.w;
    }
#pragma unroll
    for (int off = 16; off > 0; off >>= 1) s += __shfl_xor_sync(0xffffffffu, s, off);
    if (lane == 0) out[row] = s;
}

__global__ void impacts_final(const float* __restrict__ spart, const float* __restrict__ rowsq,
                              float* __restrict__ out){
    int idx = blockIdx.x * 256 + threadIdx.x;
    if (idx >= BATCH * INTER) return;
    int i = idx % INTER;
    out[idx] = sqrtf(spart[idx] * rowsq[i]);
}

// ---------------- launch ----------------
extern "C" void kernel_launch(void* const* d_in, const int* in_sizes, int n_in,
                              void* d_out, int out_size)
{
    const float* X  = (const float*)d_in[0];
    const float* Wg = (const float*)d_in[1];
    const float* Wu = (const float*)d_in[2];
    const float* Wd = (const float*)d_in[3];
    float* out = (float*)d_out;

    __half *Xh, *Wgh, *Wuh, *Wdh, *inter;
    float *rsq, *spart;
    cudaGetSymbolAddress((void**)&Xh,  g_Xh);
    cudaGetSymbolAddress((void**)&Wgh, g_Wgh);
    cudaGetSymbolAddress((void**)&Wuh, g_Wuh);
    cudaGetSymbolAddress((void**)&Wdh, g_Wdh);
    cudaGetSymbolAddress((void**)&inter, g_inter);
    cudaGetSymbolAddress((void**)&rsq, g_rowsq);
    cudaGetSymbolAddress((void**)&spart, g_s);

    cudaFuncSetAttribute(gemm_gu,   cudaFuncAttributeMaxDynamicSharedMemorySize, GU_SMEM_BYTES);
    cudaFuncSetAttribute(gemm_down, cudaFuncAttributeMaxDynamicSharedMemorySize, DN_SMEM_BYTES);

    long nX = (long)MTOK * HID / 4, nW = (long)INTER * HID / 4;

    // zero impacts accumulator (memset node; graph-capturable)
    cudaMemsetAsync(spart, 0, BATCH*INTER*sizeof(float));

    cvt_h_kernel<<<(unsigned)((nX + 255)/256), 256>>>((const float4*)X,  (__half2*)Xh,  nX);
    cvt_h_kernel<<<(unsigned)((nW + 255)/256), 256>>>((const float4*)Wg, (__half2*)Wgh, nW);
    cvt_h_kernel<<<(unsigned)((nW + 255)/256), 256>>>((const float4*)Wu, (__half2*)Wuh, nW);

    // kernel-launch #4 (ncu capture target)
    gemm_gu<<<(INTER/64)*(MTOK/128), 256, GU_SMEM_BYTES>>>(Xh, Wgh, Wuh, inter, spart);

    cvt_h_kernel<<<(unsigned)((nW + 255)/256), 256>>>((const float4*)Wd, (__half2*)Wdh, nW);

    rowsq_kernel<<<(INTER + 7)/8, 256>>>(Wu, rsq);
    impacts_final<<<(BATCH*INTER + 255)/256, 256>>>(spart, rsq, out + OUT_ELEMS);

    gemm_down<<<(HID/128)*(MTOK/128), 256, DN_SMEM_BYTES>>>(inter, Wdh, out);
}